// round 15
// baseline (speedup 1.0000x reference)
#include <cuda_runtime.h>

#define NN 65536
#define KK 16
#define CC 64
#define C8 8
#define EE (NN*KK)
#define BNEPS 1e-5f

typedef unsigned long long u64;
__device__ __forceinline__ u64 pk2(float lo, float hi) {
    u64 r; asm("mov.b64 %0, {%1,%2};" : "=l"(r) : "f"(lo), "f"(hi)); return r;
}
__device__ __forceinline__ void up2(u64 v, float& a, float& b) {
    asm("mov.b64 {%0,%1}, %2;" : "=f"(a), "=f"(b) : "l"(v));
}
__device__ __forceinline__ u64 f2(u64 a, u64 b, u64 c) {
    u64 d; asm("fma.rn.f32x2 %0, %1, %2, %3;" : "=l"(d) : "l"(a), "l"(b), "l"(c)); return d;
}
__device__ __forceinline__ u64 ad2(u64 x, u64 y) {
    u64 d; asm("add.rn.f32x2 %0, %1, %2;" : "=l"(d) : "l"(x), "l"(y)); return d;
}
#define SIGN2 0x8000000080000000ull

// ---- persistent scratch ----
__device__ double g_sum[6*64];
__device__ double g_ssq[6*64];
// slots: 0 bn1 | 1 posBN(3) | 2 attn_bn1 | 3 attn_bn2(8) | 4 bn2 | 5 bn3

__device__ float g_t   [NN*CC];
__device__ float g_asrc[NN*CC];
__device__ float g_adst[NN*CC];
__device__ float g_hW  [NN*CC];
__device__ float g_aggr[NN*CC];
__device__ float g_t3  [NN*CC];
__device__ float g_a1  [EE*C8];
__device__ float g_pe  [3*EE];   // planar raw pos-MLP outputs

// ---------------------------------------------------------------------------
__global__ void k_zero() {
    int i = threadIdx.x;
    if (i < 384) { g_sum[i] = 0.0; g_ssq[i] = 0.0; }
}

// ---------------------------------------------------------------------------
// 64-wide GEMM: 128 rows/block, 256 threads, 4 rows x 8 cols per thread.
// FFMA2 inner loop. Up to 3 weight matrices share one input tile.
__global__ __launch_bounds__(256) void k_gemm(
        const float* __restrict__ in,
        const float* __restrict__ W0, const float* __restrict__ b0, float* __restrict__ o0,
        const float* __restrict__ W1, const float* __restrict__ b1, float* __restrict__ o1,
        const float* __restrict__ W2, const float* __restrict__ b2, float* __restrict__ o2,
        int pre, const float* __restrict__ preG, const float* __restrict__ preB,
        int stat) {
    __shared__ __align__(16) float shT[128][68];
    __shared__ __align__(16) float shW[64][68];   // quad-permuted within row
    __shared__ float shPre[2][64];
    __shared__ float shS[2][64];
    int tid = threadIdx.x;
    int row0 = blockIdx.x * 128;

    if (pre >= 0 && tid < 64) {
        double mu  = g_sum[pre*64+tid] * (1.0/NN);
        double var = g_ssq[pre*64+tid] * (1.0/NN) - mu*mu;
        float sc = preG[tid] * rsqrtf((float)var + BNEPS);
        shPre[0][tid] = sc;
        shPre[1][tid] = preB[tid] - (float)mu * sc;
    }
    if (stat >= 0 && tid < 64) { shS[0][tid] = 0.f; shS[1][tid] = 0.f; }
    __syncthreads();

    for (int idx = tid; idx < 2048; idx += 256) {
        int r = idx >> 4, i4 = (idx & 15) * 4;
        float4 v = *(const float4*)&in[(row0 + r)*64 + i4];
        if (pre >= 0) {
            v.x = fmaxf(fmaf(v.x, shPre[0][i4+0], shPre[1][i4+0]), 0.f);
            v.y = fmaxf(fmaf(v.y, shPre[0][i4+1], shPre[1][i4+1]), 0.f);
            v.z = fmaxf(fmaf(v.z, shPre[0][i4+2], shPre[1][i4+2]), 0.f);
            v.w = fmaxf(fmaf(v.w, shPre[0][i4+3], shPre[1][i4+3]), 0.f);
        }
        *(float4*)&shT[r][i4] = v;
    }

    int w = tid >> 5, lane = tid & 31;
    int g = lane >> 3, t = lane & 7;
    int rbase = w*16 + g;
    int c0 = t * 8;

    #pragma unroll 1
    for (int m = 0; m < 3; m++) {
        const float* W    = (m==0) ? W0 : ((m==1) ? W1 : W2);
        if (!W) break;
        const float* bias = (m==0) ? b0 : ((m==1) ? b1 : b2);
        float* out        = (m==0) ? o0 : ((m==1) ? o1 : o2);

        __syncthreads();
        for (int idx = tid; idx < 4096; idx += 256) {
            int o = idx >> 6, k = idx & 63;
            int q = o >> 2;
            int po = (((q >> 1) + ((q & 1) << 3)) << 2) + (o & 3);
            shW[k][po] = W[idx];
        }
        __syncthreads();

        u64 acc2[4][4] = {};
        #pragma unroll 4
        for (int k = 0; k < 64; k++) {
            ulonglong2 B0 = *(const ulonglong2*)&shW[k][t*4];
            ulonglong2 B1 = *(const ulonglong2*)&shW[k][32 + t*4];
            #pragma unroll
            for (int i = 0; i < 4; i++) {
                float av = shT[rbase + 4*i][k];
                u64 av2 = pk2(av, av);
                acc2[i][0] = f2(av2, B0.x, acc2[i][0]);
                acc2[i][1] = f2(av2, B0.y, acc2[i][1]);
                acc2[i][2] = f2(av2, B1.x, acc2[i][2]);
                acc2[i][3] = f2(av2, B1.y, acc2[i][3]);
            }
        }
        float bb[8];
        #pragma unroll
        for (int j = 0; j < 8; j++) bb[j] = bias ? bias[c0+j] : 0.f;
        float s[8] = {}, q2[8] = {};
        #pragma unroll
        for (int i = 0; i < 4; i++) {
            int rr = row0 + rbase + 4*i;
            float v[8];
            up2(acc2[i][0], v[0], v[1]);
            up2(acc2[i][1], v[2], v[3]);
            up2(acc2[i][2], v[4], v[5]);
            up2(acc2[i][3], v[6], v[7]);
            #pragma unroll
            for (int j = 0; j < 8; j++) { v[j] += bb[j]; s[j] += v[j]; q2[j] += v[j]*v[j]; }
            *(float4*)&out[rr*64 + c0]     = make_float4(v[0],v[1],v[2],v[3]);
            *(float4*)&out[rr*64 + c0 + 4] = make_float4(v[4],v[5],v[6],v[7]);
        }
        if (stat >= 0) {
            #pragma unroll
            for (int j = 0; j < 8; j++) {
                s[j]  += __shfl_xor_sync(0xffffffffu, s[j], 8);
                s[j]  += __shfl_xor_sync(0xffffffffu, s[j], 16);
                q2[j] += __shfl_xor_sync(0xffffffffu, q2[j], 8);
                q2[j] += __shfl_xor_sync(0xffffffffu, q2[j], 16);
            }
            if (g == 0) {
                #pragma unroll
                for (int j = 0; j < 8; j++) {
                    atomicAdd(&shS[0][c0+j], s[j]);
                    atomicAdd(&shS[1][c0+j], q2[j]);
                }
            }
            __syncthreads();
            if (tid < 64) {
                atomicAdd(&g_sum[stat*64+tid], (double)shS[0][tid]);
                atomicAdd(&g_ssq[stat*64+tid], (double)shS[1][tid]);
            }
        }
    }
}

// ---------------------------------------------------------------------------
// Fused front: blocks [0,512) compute t = x @ W_in^T (+ bn1 stats, slot 0);
// blocks [512,1536) run the pos-MLP edge pass (g_pe + posBN stats, slot 1).
__global__ __launch_bounds__(256) void k_front(
        const float* __restrict__ x, const float* __restrict__ W_in,
        float* __restrict__ t_out,
        const float* __restrict__ pos, const int* __restrict__ src,
        const float* __restrict__ pw1, const float* __restrict__ pb1) {
    __shared__ __align__(16) float shT[128][68];
    __shared__ __align__(16) float shW[64][68];
    __shared__ float shS[2][64];
    int tid = threadIdx.x;

    if (blockIdx.x < 512) {
        int row0 = blockIdx.x * 128;
        if (tid < 64) { shS[0][tid] = 0.f; shS[1][tid] = 0.f; }

        for (int idx = tid; idx < 2048; idx += 256) {
            int r = idx >> 4, i4 = (idx & 15) * 4;
            float4 v = *(const float4*)&x[(row0 + r)*64 + i4];
            *(float4*)&shT[r][i4] = v;
        }
        for (int idx = tid; idx < 4096; idx += 256) {
            int o = idx >> 6, k = idx & 63;
            int q = o >> 2;
            int po = (((q >> 1) + ((q & 1) << 3)) << 2) + (o & 3);
            shW[k][po] = W_in[idx];
        }
        __syncthreads();

        int w = tid >> 5, lane = tid & 31;
        int g = lane >> 3, t = lane & 7;
        int rbase = w*16 + g;
        int c0 = t * 8;

        u64 acc2[4][4] = {};
        #pragma unroll 4
        for (int k = 0; k < 64; k++) {
            ulonglong2 B0 = *(const ulonglong2*)&shW[k][t*4];
            ulonglong2 B1 = *(const ulonglong2*)&shW[k][32 + t*4];
            #pragma unroll
            for (int i = 0; i < 4; i++) {
                float av = shT[rbase + 4*i][k];
                u64 av2 = pk2(av, av);
                acc2[i][0] = f2(av2, B0.x, acc2[i][0]);
                acc2[i][1] = f2(av2, B0.y, acc2[i][1]);
                acc2[i][2] = f2(av2, B1.x, acc2[i][2]);
                acc2[i][3] = f2(av2, B1.y, acc2[i][3]);
            }
        }
        float s[8] = {}, q2[8] = {};
        #pragma unroll
        for (int i = 0; i < 4; i++) {
            int rr = row0 + rbase + 4*i;
            float v[8];
            up2(acc2[i][0], v[0], v[1]);
            up2(acc2[i][1], v[2], v[3]);
            up2(acc2[i][2], v[4], v[5]);
            up2(acc2[i][3], v[6], v[7]);
            #pragma unroll
            for (int j = 0; j < 8; j++) { s[j] += v[j]; q2[j] += v[j]*v[j]; }
            *(float4*)&t_out[rr*64 + c0]     = make_float4(v[0],v[1],v[2],v[3]);
            *(float4*)&t_out[rr*64 + c0 + 4] = make_float4(v[4],v[5],v[6],v[7]);
        }
        #pragma unroll
        for (int j = 0; j < 8; j++) {
            s[j]  += __shfl_xor_sync(0xffffffffu, s[j], 8);
            s[j]  += __shfl_xor_sync(0xffffffffu, s[j], 16);
            q2[j] += __shfl_xor_sync(0xffffffffu, q2[j], 8);
            q2[j] += __shfl_xor_sync(0xffffffffu, q2[j], 16);
        }
        int g2 = (tid & 31) >> 3;
        if (g2 == 0) {
            #pragma unroll
            for (int j = 0; j < 8; j++) {
                atomicAdd(&shS[0][c0+j], s[j]);
                atomicAdd(&shS[1][c0+j], q2[j]);
            }
        }
        __syncthreads();
        if (tid < 64) {
            atomicAdd(&g_sum[tid], (double)shS[0][tid]);
            atomicAdd(&g_ssq[tid], (double)shS[1][tid]);
        }
    } else {
        float w00=pw1[0],w01=pw1[1],w02=pw1[2];
        float w10=pw1[3],w11=pw1[4],w12=pw1[5];
        float w20=pw1[6],w21=pw1[7],w22=pw1[8];
        float b0=pb1[0],b1=pb1[1],b2=pb1[2];
        float s0=0,s1=0,s2=0,q0=0,q1=0,q2=0;
        int pbid = blockIdx.x - 512;
        int stride = 1024*256;
        for (int e = pbid*256 + tid; e < EE; e += stride) {
            int sj = src[e]; int di = e >> 4;
            float rx = pos[sj*3+0]-pos[di*3+0];
            float ry = pos[sj*3+1]-pos[di*3+1];
            float rz = pos[sj*3+2]-pos[di*3+2];
            float v0 = fmaf(rx,w00,fmaf(ry,w01,fmaf(rz,w02,b0)));
            float v1 = fmaf(rx,w10,fmaf(ry,w11,fmaf(rz,w12,b1)));
            float v2 = fmaf(rx,w20,fmaf(ry,w21,fmaf(rz,w22,b2)));
            g_pe[e] = v0; g_pe[EE+e] = v1; g_pe[2*EE+e] = v2;
            s0+=v0; q0+=v0*v0; s1+=v1; q1+=v1*v1; s2+=v2; q2+=v2*v2;
        }
        if (tid < 6) shS[0][tid]=0.f;
        __syncthreads();
        #pragma unroll
        for (int o = 16; o; o >>= 1) {
            s0+=__shfl_xor_sync(~0u,s0,o); s1+=__shfl_xor_sync(~0u,s1,o); s2+=__shfl_xor_sync(~0u,s2,o);
            q0+=__shfl_xor_sync(~0u,q0,o); q1+=__shfl_xor_sync(~0u,q1,o); q2+=__shfl_xor_sync(~0u,q2,o);
        }
        if ((tid & 31) == 0) {
            atomicAdd(&shS[0][0],s0); atomicAdd(&shS[0][1],s1); atomicAdd(&shS[0][2],s2);
            atomicAdd(&shS[0][3],q0); atomicAdd(&shS[0][4],q1); atomicAdd(&shS[0][5],q2);
        }
        __syncthreads();
        if (tid < 3) {
            atomicAdd(&g_sum[64+tid], (double)shS[0][tid]);
            atomicAdd(&g_ssq[64+tid], (double)shS[0][tid+3]);
        }
    }
}

// ---------------------------------------------------------------------------
__device__ __forceinline__ void compute_pos_bn(float* sP, const float* pbnG, const float* pbnB, int tid) {
    if (tid < 3) {
        double mu  = g_sum[64+tid] * (1.0/EE);
        double var = g_ssq[64+tid] * (1.0/EE) - mu*mu;
        float sc = pbnG[tid] * rsqrtf((float)var + BNEPS);
        sP[tid] = sc; sP[3+tid] = pbnB[tid] - (float)mu*sc;
    }
}

// ---------------------------------------------------------------------------
// stats of a = a_src[src] - a_dst[dst] + delta over E (slot 2). f32x2 math.
// min-3-blocks/SM to raise occupancy (latency-bound: occ 23%, issue 25%).
__global__ __launch_bounds__(256, 3) void k_attn1_stats(const int* __restrict__ src,
        const float* __restrict__ pw2, const float* __restrict__ pb2,
        const float* __restrict__ pbnG, const float* __restrict__ pbnB) {
    __shared__ float sh[2][64];
    __shared__ float sP[6];
    int tid = threadIdx.x, lane = tid & 31;
    compute_pos_bn(sP, pbnG, pbnB, tid);
    __syncthreads();
    int l = lane & 15, hl = lane >> 4;
    int c4 = l * 4;
    u64 PA[3], PB[3];
    #pragma unroll
    for (int k = 0; k < 3; k++) {
        PA[k] = pk2(pw2[(c4+0)*3+k], pw2[(c4+1)*3+k]);
        PB[k] = pk2(pw2[(c4+2)*3+k], pw2[(c4+3)*3+k]);
    }
    u64 Ab01 = pk2(pb2[c4+0], pb2[c4+1]);
    u64 Ab23 = pk2(pb2[c4+2], pb2[c4+3]);
    float ps0=sP[0],ps1=sP[1],ps2=sP[2];
    float pB0=sP[3],pB1=sP[4],pB2=sP[5];
    u64 s01=0, s23=0, q01=0, q23=0;
    int wId = (blockIdx.x*256 + tid) >> 5;
    int nW  = (gridDim.x*256) >> 5;
    for (int n = wId; n < NN; n += nW) {
        ulonglong2 adv = *(const ulonglong2*)&g_adst[n*64 + c4];
        u64 AbAd01 = ad2(Ab01, adv.x ^ SIGN2);
        u64 AbAd23 = ad2(Ab23, adv.y ^ SIGN2);
        int sv = src[n*16 + l];
        #pragma unroll
        for (int jj = 0; jj < 8; jj++) {
            int ei = jj*2 + hl;
            int e  = n*16 + ei;
            int sj = __shfl_sync(0xffffffffu, sv, ei);
            float d0 = fmaxf(fmaf(g_pe[e],      ps0, pB0), 0.f);
            float d1 = fmaxf(fmaf(g_pe[EE+e],   ps1, pB1), 0.f);
            float d2 = fmaxf(fmaf(g_pe[2*EE+e], ps2, pB2), 0.f);
            u64 D0 = pk2(d0,d0), D1 = pk2(d1,d1), D2 = pk2(d2,d2);
            ulonglong2 asv = *(const ulonglong2*)&g_asrc[sj*64 + c4];
            u64 a01 = ad2(asv.x, f2(D0,PA[0], f2(D1,PA[1], f2(D2,PA[2], AbAd01))));
            u64 a23 = ad2(asv.y, f2(D0,PB[0], f2(D1,PB[1], f2(D2,PB[2], AbAd23))));
            s01 = ad2(s01, a01); q01 = f2(a01, a01, q01);
            s23 = ad2(s23, a23); q23 = f2(a23, a23, q23);
        }
    }
    float s[4], q[4];
    up2(s01, s[0], s[1]); up2(s23, s[2], s[3]);
    up2(q01, q[0], q[1]); up2(q23, q[2], q[3]);
    if (tid < 128) sh[tid>>6][tid&63] = 0.f;
    __syncthreads();
    #pragma unroll
    for (int i = 0; i < 4; i++) {
        s[i] += __shfl_xor_sync(0xffffffffu, s[i], 16);
        q[i] += __shfl_xor_sync(0xffffffffu, q[i], 16);
    }
    if (hl == 0) {
        #pragma unroll
        for (int i = 0; i < 4; i++) {
            atomicAdd(&sh[0][c4+i], s[i]);
            atomicAdd(&sh[1][c4+i], q[i]);
        }
    }
    __syncthreads();
    if (tid < 64) {
        atomicAdd(&g_sum[128+tid], (double)sh[0][tid]);
        atomicAdd(&g_ssq[128+tid], (double)sh[1][tid]);
    }
}

// ---------------------------------------------------------------------------
// a1 = relu(bn(a)) @ attn_w1^T + b1 -> g_a1 [E,8]; stats slot 3.
__global__ __launch_bounds__(256) void k_a1(const int* __restrict__ src,
        const float* __restrict__ pw2, const float* __restrict__ pb2,
        const float* __restrict__ aw1, const float* __restrict__ ab1,
        const float* __restrict__ pbnG, const float* __restrict__ pbnB,
        const float* __restrict__ a1G, const float* __restrict__ a1B) {
    __shared__ float shQ[2][8];
    __shared__ float sP[6];
    __shared__ float sA[2][64];
    int tid = threadIdx.x, lane = tid & 31;
    compute_pos_bn(sP, pbnG, pbnB, tid);
    if (tid < 64) {
        double mu  = g_sum[128+tid] * (1.0/EE);
        double var = g_ssq[128+tid] * (1.0/EE) - mu*mu;
        float sc = a1G[tid] * rsqrtf((float)var + BNEPS);
        sA[0][tid] = sc; sA[1][tid] = a1B[tid] - (float)mu*sc;
    }
    __syncthreads();
    int l = lane & 15, hl = lane >> 4;
    int c4 = l * 4;
    u64 PA[3], PB[3];
    #pragma unroll
    for (int k = 0; k < 3; k++) {
        PA[k] = pk2(pw2[(c4+0)*3+k], pw2[(c4+1)*3+k]);
        PB[k] = pk2(pw2[(c4+2)*3+k], pw2[(c4+3)*3+k]);
    }
    u64 Ab01 = pk2(pb2[c4+0], pb2[c4+1]);
    u64 Ab23 = pk2(pb2[c4+2], pb2[c4+3]);
    float ps0=sP[0],ps1=sP[1],ps2=sP[2];
    float pB0=sP[3],pB1=sP[4],pB2=sP[5];
    float sc[4], sb[4];
    #pragma unroll
    for (int i = 0; i < 4; i++) { sc[i]=sA[0][c4+i]; sb[i]=sA[1][c4+i]; }
    u64 WT[4][4];
    #pragma unroll
    for (int jp = 0; jp < 4; jp++)
        #pragma unroll
        for (int c = 0; c < 4; c++)
            WT[c][jp] = pk2(aw1[(2*jp)*64 + c4 + c], aw1[(2*jp+1)*64 + c4 + c]);
    int jown = l >> 1;
    float bj = ab1[jown];
    float st = 0.f, sq = 0.f;
    int wId = (blockIdx.x*256 + tid) >> 5;
    int nW  = (gridDim.x*256) >> 5;
    for (int n = wId; n < NN; n += nW) {
        ulonglong2 adv = *(const ulonglong2*)&g_adst[n*64 + c4];
        u64 AbAd01 = ad2(Ab01, adv.x ^ SIGN2);
        u64 AbAd23 = ad2(Ab23, adv.y ^ SIGN2);
        int sv = src[n*16 + l];
        #pragma unroll
        for (int jj = 0; jj < 8; jj++) {
            int ei = jj*2 + hl;
            int e  = n*16 + ei;
            int sj = __shfl_sync(0xffffffffu, sv, ei);
            float d0 = fmaxf(fmaf(g_pe[e],      ps0, pB0), 0.f);
            float d1 = fmaxf(fmaf(g_pe[EE+e],   ps1, pB1), 0.f);
            float d2 = fmaxf(fmaf(g_pe[2*EE+e], ps2, pB2), 0.f);
            u64 D0 = pk2(d0,d0), D1 = pk2(d1,d1), D2 = pk2(d2,d2);
            ulonglong2 asv = *(const ulonglong2*)&g_asrc[sj*64 + c4];
            u64 a01 = ad2(asv.x, f2(D0,PA[0], f2(D1,PA[1], f2(D2,PA[2], AbAd01))));
            u64 a23 = ad2(asv.y, f2(D0,PB[0], f2(D1,PB[1], f2(D2,PB[2], AbAd23))));
            float aa0, aa1, aa2, aa3;
            up2(a01, aa0, aa1); up2(a23, aa2, aa3);
            float r0 = fmaxf(fmaf(aa0, sc[0], sb[0]), 0.f);
            float r1 = fmaxf(fmaf(aa1, sc[1], sb[1]), 0.f);
            float r2 = fmaxf(fmaf(aa2, sc[2], sb[2]), 0.f);
            float r3 = fmaxf(fmaf(aa3, sc[3], sb[3]), 0.f);
            u64 R0 = pk2(r0,r0), R1 = pk2(r1,r1), R2 = pk2(r2,r2), R3 = pk2(r3,r3);
            float p[8];
            #pragma unroll
            for (int jp = 0; jp < 4; jp++) {
                u64 t2 = f2(R0, WT[0][jp], f2(R1, WT[1][jp], f2(R2, WT[2][jp], f2(R3, WT[3][jp], 0ull))));
                up2(t2, p[2*jp], p[2*jp+1]);
            }
            #pragma unroll
            for (int j = 0; j < 4; j++) {
                float v = (l & 8) ? p[j] : p[j+4];
                float ww = __shfl_xor_sync(0xffffffffu, v, 8);
                p[j] = ((l & 8) ? p[j+4] : p[j]) + ww;
            }
            #pragma unroll
            for (int j = 0; j < 2; j++) {
                float v = (l & 4) ? p[j] : p[j+2];
                float ww = __shfl_xor_sync(0xffffffffu, v, 4);
                p[j] = ((l & 4) ? p[j+2] : p[j]) + ww;
            }
            {
                float v = (l & 2) ? p[0] : p[1];
                float ww = __shfl_xor_sync(0xffffffffu, v, 2);
                p[0] = ((l & 2) ? p[1] : p[0]) + ww;
            }
            p[0] += __shfl_xor_sync(0xffffffffu, p[0], 1);
            float vv = p[0] + bj;
            if ((l & 1) == 0) {
                g_a1[e*8 + jown] = vv;
                st += vv; sq += vv*vv;
            }
        }
    }
    if (tid < 16) shQ[tid>>3][tid&7] = 0.f;
    __syncthreads();
    if ((l & 1) == 0) { atomicAdd(&shQ[0][jown], st); atomicAdd(&shQ[1][jown], sq); }
    __syncthreads();
    if (tid < 8) {
        atomicAdd(&g_sum[192+tid], (double)shQ[0][tid]);
        atomicAdd(&g_ssq[192+tid], (double)shQ[1][tid]);
    }
}

// ---------------------------------------------------------------------------
// Warp-per-node: a2 from a1, softmax (16 edges), weighted aggregation; stats slot 4.
__global__ __launch_bounds__(256) void k_aggr(const int* __restrict__ src,
        const float* __restrict__ pw2, const float* __restrict__ pb2,
        const float* __restrict__ aw2, const float* __restrict__ ab2,
        const float* __restrict__ pbnG, const float* __restrict__ pbnB,
        const float* __restrict__ a2G, const float* __restrict__ a2B) {
    __shared__ float sh_alpha[8][16][8];
    __shared__ float sh_d[8][16][3];
    __shared__ float shS[2][64];
    __shared__ float sP[6];
    __shared__ float sB[2][8];
    int tid = threadIdx.x, lane = tid & 31, w = tid >> 5;
    compute_pos_bn(sP, pbnG, pbnB, tid);
    if (tid < 8) {
        double mu  = g_sum[192+tid] * (1.0/EE);
        double var = g_ssq[192+tid] * (1.0/EE) - mu*mu;
        float sc = a2G[tid] * rsqrtf((float)var + BNEPS);
        sB[0][tid] = sc; sB[1][tid] = a2B[tid] - (float)mu*sc;
    }
    if (tid < 128) shS[tid>>6][tid&63] = 0.f;
    __syncthreads();
    int c = lane, c2 = lane + 32;
    float A0=pw2[c*3],  A1=pw2[c*3+1],  A2=pw2[c*3+2],  Abc=pb2[c];
    float B0=pw2[c2*3], B1=pw2[c2*3+1], B2=pw2[c2*3+2], Bbc=pb2[c2];
    float ps0=sP[0],ps1=sP[1],ps2=sP[2];
    float pB0=sP[3],pB1=sP[4],pB2=sP[5];
    int e = lane >> 1, j4 = (lane & 1) * 4;
    float s3[4], b3[4];
    #pragma unroll
    for (int i = 0; i < 4; i++) { s3[i]=sB[0][j4+i]; b3[i]=sB[1][j4+i]; }
    float4 w2v[8];
    #pragma unroll
    for (int j = 0; j < 8; j++) w2v[j] = *(const float4*)&aw2[j*8 + j4];
    float b2v[8];
    #pragma unroll
    for (int j = 0; j < 8; j++) b2v[j] = ab2[j];
    int j8 = lane & 7;
    float st=0, sq=0, st2=0, sq2=0;
    int wId = blockIdx.x*8 + w, nW = gridDim.x*8;
    for (int n = wId; n < NN; n += nW) {
        int sv = src[n*16 + (lane & 15)];
        if (lane < 16) {
            int ee = n*16 + lane;
            sh_d[w][lane][0] = fmaxf(fmaf(g_pe[ee],      ps0, pB0), 0.f);
            sh_d[w][lane][1] = fmaxf(fmaf(g_pe[EE+ee],   ps1, pB1), 0.f);
            sh_d[w][lane][2] = fmaxf(fmaf(g_pe[2*EE+ee], ps2, pB2), 0.f);
        }
        float4 bv = *(const float4*)&g_a1[n*128 + lane*4];
        float bb0 = fmaxf(fmaf(bv.x, s3[0], b3[0]), 0.f);
        float bb1 = fmaxf(fmaf(bv.y, s3[1], b3[1]), 0.f);
        float bb2 = fmaxf(fmaf(bv.z, s3[2], b3[2]), 0.f);
        float bb3 = fmaxf(fmaf(bv.w, s3[3], b3[3]), 0.f);
        float p[8];
        #pragma unroll
        for (int j = 0; j < 8; j++)
            p[j] = fmaf(bb0, w2v[j].x, fmaf(bb1, w2v[j].y, fmaf(bb2, w2v[j].z, bb3 * w2v[j].w)));
        #pragma unroll
        for (int j = 0; j < 8; j++) p[j] += __shfl_xor_sync(0xffffffffu, p[j], 1);
        if ((lane & 1) == 0) {
            #pragma unroll
            for (int j = 0; j < 8; j++) sh_alpha[w][e][j] = p[j] + b2v[j];
        }
        __syncwarp();
        if (lane < 8) {
            float mx = -1e30f;
            #pragma unroll
            for (int t = 0; t < 16; t++) mx = fmaxf(mx, sh_alpha[w][t][lane]);
            float ex[16], sm = 0.f;
            #pragma unroll
            for (int t = 0; t < 16; t++) { ex[t] = __expf(sh_alpha[w][t][lane]-mx); sm += ex[t]; }
            float inv = 1.f/sm;
            #pragma unroll
            for (int t = 0; t < 16; t++) sh_alpha[w][t][lane] = ex[t]*inv;
        }
        __syncwarp();
        float acc = 0.f, acc2 = 0.f;
        #pragma unroll
        for (int t = 0; t < 16; t++) {
            int sj = __shfl_sync(0xffffffffu, sv, t);
            float hw  = g_hW[sj*64 + c];
            float hw2 = g_hW[sj*64 + c2];
            float d0 = sh_d[w][t][0], d1 = sh_d[w][t][1], d2 = sh_d[w][t][2];
            float al = sh_alpha[w][t][j8];
            acc  = fmaf(al, hw  + fmaf(d0,A0,fmaf(d1,A1,fmaf(d2,A2,Abc))), acc);
            acc2 = fmaf(al, hw2 + fmaf(d0,B0,fmaf(d1,B1,fmaf(d2,B2,Bbc))), acc2);
        }
        g_aggr[n*64 + c]  = acc;
        g_aggr[n*64 + c2] = acc2;
        st += acc; sq += acc*acc; st2 += acc2; sq2 += acc2*acc2;
        __syncwarp();
    }
    __syncthreads();
    atomicAdd(&shS[0][c],  st);  atomicAdd(&shS[1][c],  sq);
    atomicAdd(&shS[0][c2], st2); atomicAdd(&shS[1][c2], sq2);
    __syncthreads();
    if (tid < 64) {
        atomicAdd(&g_sum[256+tid], (double)shS[0][tid]);
        atomicAdd(&g_ssq[256+tid], (double)shS[1][tid]);
    }
}

// ---------------------------------------------------------------------------
__global__ __launch_bounds__(256) void k_final(const float* __restrict__ x,
        const float* __restrict__ g, const float* __restrict__ b,
        float* __restrict__ out) {
    __shared__ float sSc[64], sBi[64];
    int tid = threadIdx.x;
    if (tid < 64) {
        double mu  = g_sum[5*64+tid] * (1.0/NN);
        double var = g_ssq[5*64+tid] * (1.0/NN) - mu*mu;
        float sc = g[tid] * rsqrtf((float)var + BNEPS);
        sSc[tid] = sc; sBi[tid] = b[tid] - (float)mu*sc;
    }
    __syncthreads();
    int stride = gridDim.x * blockDim.x;
    for (int i4 = blockIdx.x*blockDim.x + tid; i4 < NN*16; i4 += stride) {
        float4 v  = *(const float4*)&g_t3[i4*4];
        float4 xv = *(const float4*)&x[i4*4];
        int cg = (i4 & 15) * 4;
        float4 r;
        r.x = fmaxf(fmaf(v.x, sSc[cg+0], sBi[cg+0]) + xv.x, 0.f);
        r.y = fmaxf(fmaf(v.y, sSc[cg+1], sBi[cg+1]) + xv.y, 0.f);
        r.z = fmaxf(fmaf(v.z, sSc[cg+2], sBi[cg+2]) + xv.z, 0.f);
        r.w = fmaxf(fmaf(v.w, sSc[cg+3], sBi[cg+3]) + xv.w, 0.f);
        *(float4*)&out[i4*4] = r;
    }
}

// ---------------------------------------------------------------------------
extern "C" void kernel_launch(void* const* d_in, const int* in_sizes, int n_in,
                              void* d_out, int out_size) {
    const float* x      = (const float*)d_in[0];
    const float* pos    = (const float*)d_in[1];
    const int*   src    = (const int*)  d_in[2];
    const float* W_in   = (const float*)d_in[3];
    const float* W_out  = (const float*)d_in[4];
    const float* pw1    = (const float*)d_in[5];
    const float* pb1    = (const float*)d_in[6];
    const float* pbn_g  = (const float*)d_in[7];
    const float* pbn_b  = (const float*)d_in[8];
    const float* pw2    = (const float*)d_in[9];
    const float* pb2    = (const float*)d_in[10];
    const float* abn1_g = (const float*)d_in[11];
    const float* abn1_b = (const float*)d_in[12];
    const float* aw1    = (const float*)d_in[13];
    const float* ab1    = (const float*)d_in[14];
    const float* abn2_g = (const float*)d_in[15];
    const float* abn2_b = (const float*)d_in[16];
    const float* aw2    = (const float*)d_in[17];
    const float* ab2    = (const float*)d_in[18];
    const float* lin_w  = (const float*)d_in[19];
    const float* lin_b  = (const float*)d_in[20];
    const float* src_w  = (const float*)d_in[21];
    const float* src_b  = (const float*)d_in[22];
    const float* dst_w  = (const float*)d_in[23];
    const float* dst_b  = (const float*)d_in[24];
    const float* bn1_g  = (const float*)d_in[25];
    const float* bn1_b  = (const float*)d_in[26];
    const float* bn2_g  = (const float*)d_in[27];
    const float* bn2_b  = (const float*)d_in[28];
    const float* bn3_g  = (const float*)d_in[29];
    const float* bn3_b  = (const float*)d_in[30];
    float* out = (float*)d_out;

    float *p_t, *p_asrc, *p_adst, *p_hW, *p_aggr, *p_t3;
    cudaGetSymbolAddress((void**)&p_t,    g_t);
    cudaGetSymbolAddress((void**)&p_asrc, g_asrc);
    cudaGetSymbolAddress((void**)&p_adst, g_adst);
    cudaGetSymbolAddress((void**)&p_hW,   g_hW);
    cudaGetSymbolAddress((void**)&p_aggr, g_aggr);
    cudaGetSymbolAddress((void**)&p_t3,   g_t3);

    k_zero<<<1,384>>>();

    // fused: t = x @ W_in^T (+ bn1 stats)  ||  pos MLP + posBN stats
    k_front<<<1536,256>>>(x, W_in, p_t, pos, src, pw1, pb1);

    // a_src/a_dst/hW = relu(bn1(t)) @ {src_w,dst_w,lin_w}^T + bias (fused triple)
    k_gemm<<<512,256>>>(p_t, src_w, src_b, p_asrc,
                        dst_w, dst_b, p_adst,
                        lin_w, lin_b, p_hW,
                        0, bn1_g, bn1_b, -1);

    // attn_bn1 stats over edges
    k_attn1_stats<<<1024,256>>>(src, pw2, pb2, pbn_g, pbn_b);

    // a1 ; attn_bn2 stats
    k_a1<<<1024,256>>>(src, pw2, pb2, aw1, ab1, pbn_g, pbn_b, abn1_g, abn1_b);

    // softmax + aggregation ; bn2 stats
    k_aggr<<<1024,256>>>(src, pw2, pb2, aw2, ab2, pbn_g, pbn_b, abn2_g, abn2_b);

    // t3 = relu(bn2(aggr)) @ W_out^T ; bn3 stats
    k_gemm<<<512,256>>>(p_aggr, W_out, nullptr, p_t3,
                        nullptr, nullptr, nullptr, nullptr, nullptr, nullptr,
                        4, bn2_g, bn2_b, 5);

    // y = relu(bn3(t3) + x)
    k_final<<<1024,256>>>(x, bn3_g, bn3_b, out);
}

// round 16
// speedup vs baseline: 1.0318x; 1.0318x over previous
#include <cuda_runtime.h>

#define NN 65536
#define KK 16
#define CC 64
#define C8 8
#define EE (NN*KK)
#define BNEPS 1e-5f

typedef unsigned long long u64;
__device__ __forceinline__ u64 pk2(float lo, float hi) {
    u64 r; asm("mov.b64 %0, {%1,%2};" : "=l"(r) : "f"(lo), "f"(hi)); return r;
}
__device__ __forceinline__ void up2(u64 v, float& a, float& b) {
    asm("mov.b64 {%0,%1}, %2;" : "=f"(a), "=f"(b) : "l"(v));
}
__device__ __forceinline__ u64 f2(u64 a, u64 b, u64 c) {
    u64 d; asm("fma.rn.f32x2 %0, %1, %2, %3;" : "=l"(d) : "l"(a), "l"(b), "l"(c)); return d;
}
__device__ __forceinline__ u64 ad2(u64 x, u64 y) {
    u64 d; asm("add.rn.f32x2 %0, %1, %2;" : "=l"(d) : "l"(x), "l"(y)); return d;
}
#define SIGN2 0x8000000080000000ull

// ---- persistent scratch ----
__device__ double g_sum[6*64];
__device__ double g_ssq[6*64];
// slots: 0 bn1 | 1 posBN(3) | 2 attn_bn1 | 3 attn_bn2(8) | 4 bn2 | 5 bn3

__device__ float g_t   [NN*CC];
__device__ float g_asrc[NN*CC];
__device__ float g_adst[NN*CC];
__device__ float g_hW  [NN*CC];
__device__ float g_aggr[NN*CC];
__device__ float g_t3  [NN*CC];
__device__ float g_a1  [EE*C8];
__device__ float g_pe  [3*EE];   // planar raw pos-MLP outputs

// ---------------------------------------------------------------------------
__global__ void k_zero() {
    int i = threadIdx.x;
    if (i < 384) { g_sum[i] = 0.0; g_ssq[i] = 0.0; }
}

// ---------------------------------------------------------------------------
// 64-wide GEMM: 128 rows/block, 256 threads, 4 rows x 8 cols per thread.
// FFMA2 inner loop. Up to 3 weight matrices share one input tile.
__global__ __launch_bounds__(256) void k_gemm(
        const float* __restrict__ in,
        const float* __restrict__ W0, const float* __restrict__ b0, float* __restrict__ o0,
        const float* __restrict__ W1, const float* __restrict__ b1, float* __restrict__ o1,
        const float* __restrict__ W2, const float* __restrict__ b2, float* __restrict__ o2,
        int pre, const float* __restrict__ preG, const float* __restrict__ preB,
        int stat) {
    __shared__ __align__(16) float shT[128][68];
    __shared__ __align__(16) float shW[64][68];   // quad-permuted within row
    __shared__ float shPre[2][64];
    __shared__ float shS[2][64];
    int tid = threadIdx.x;
    int row0 = blockIdx.x * 128;

    if (pre >= 0 && tid < 64) {
        double mu  = g_sum[pre*64+tid] * (1.0/NN);
        double var = g_ssq[pre*64+tid] * (1.0/NN) - mu*mu;
        float sc = preG[tid] * rsqrtf((float)var + BNEPS);
        shPre[0][tid] = sc;
        shPre[1][tid] = preB[tid] - (float)mu * sc;
    }
    if (stat >= 0 && tid < 64) { shS[0][tid] = 0.f; shS[1][tid] = 0.f; }
    __syncthreads();

    for (int idx = tid; idx < 2048; idx += 256) {
        int r = idx >> 4, i4 = (idx & 15) * 4;
        float4 v = *(const float4*)&in[(row0 + r)*64 + i4];
        if (pre >= 0) {
            v.x = fmaxf(fmaf(v.x, shPre[0][i4+0], shPre[1][i4+0]), 0.f);
            v.y = fmaxf(fmaf(v.y, shPre[0][i4+1], shPre[1][i4+1]), 0.f);
            v.z = fmaxf(fmaf(v.z, shPre[0][i4+2], shPre[1][i4+2]), 0.f);
            v.w = fmaxf(fmaf(v.w, shPre[0][i4+3], shPre[1][i4+3]), 0.f);
        }
        *(float4*)&shT[r][i4] = v;
    }

    int w = tid >> 5, lane = tid & 31;
    int g = lane >> 3, t = lane & 7;
    int rbase = w*16 + g;
    int c0 = t * 8;

    #pragma unroll 1
    for (int m = 0; m < 3; m++) {
        const float* W    = (m==0) ? W0 : ((m==1) ? W1 : W2);
        if (!W) break;
        const float* bias = (m==0) ? b0 : ((m==1) ? b1 : b2);
        float* out        = (m==0) ? o0 : ((m==1) ? o1 : o2);

        __syncthreads();
        for (int idx = tid; idx < 4096; idx += 256) {
            int o = idx >> 6, k = idx & 63;
            int q = o >> 2;
            int po = (((q >> 1) + ((q & 1) << 3)) << 2) + (o & 3);
            shW[k][po] = W[idx];
        }
        __syncthreads();

        u64 acc2[4][4] = {};
        #pragma unroll 4
        for (int k = 0; k < 64; k++) {
            ulonglong2 B0 = *(const ulonglong2*)&shW[k][t*4];
            ulonglong2 B1 = *(const ulonglong2*)&shW[k][32 + t*4];
            #pragma unroll
            for (int i = 0; i < 4; i++) {
                float av = shT[rbase + 4*i][k];
                u64 av2 = pk2(av, av);
                acc2[i][0] = f2(av2, B0.x, acc2[i][0]);
                acc2[i][1] = f2(av2, B0.y, acc2[i][1]);
                acc2[i][2] = f2(av2, B1.x, acc2[i][2]);
                acc2[i][3] = f2(av2, B1.y, acc2[i][3]);
            }
        }
        float bb[8];
        #pragma unroll
        for (int j = 0; j < 8; j++) bb[j] = bias ? bias[c0+j] : 0.f;
        float s[8] = {}, q2[8] = {};
        #pragma unroll
        for (int i = 0; i < 4; i++) {
            int rr = row0 + rbase + 4*i;
            float v[8];
            up2(acc2[i][0], v[0], v[1]);
            up2(acc2[i][1], v[2], v[3]);
            up2(acc2[i][2], v[4], v[5]);
            up2(acc2[i][3], v[6], v[7]);
            #pragma unroll
            for (int j = 0; j < 8; j++) { v[j] += bb[j]; s[j] += v[j]; q2[j] += v[j]*v[j]; }
            *(float4*)&out[rr*64 + c0]     = make_float4(v[0],v[1],v[2],v[3]);
            *(float4*)&out[rr*64 + c0 + 4] = make_float4(v[4],v[5],v[6],v[7]);
        }
        if (stat >= 0) {
            #pragma unroll
            for (int j = 0; j < 8; j++) {
                s[j]  += __shfl_xor_sync(0xffffffffu, s[j], 8);
                s[j]  += __shfl_xor_sync(0xffffffffu, s[j], 16);
                q2[j] += __shfl_xor_sync(0xffffffffu, q2[j], 8);
                q2[j] += __shfl_xor_sync(0xffffffffu, q2[j], 16);
            }
            if (g == 0) {
                #pragma unroll
                for (int j = 0; j < 8; j++) {
                    atomicAdd(&shS[0][c0+j], s[j]);
                    atomicAdd(&shS[1][c0+j], q2[j]);
                }
            }
            __syncthreads();
            if (tid < 64) {
                atomicAdd(&g_sum[stat*64+tid], (double)shS[0][tid]);
                atomicAdd(&g_ssq[stat*64+tid], (double)shS[1][tid]);
            }
        }
    }
}

// ---------------------------------------------------------------------------
// Fused front: blocks [0,512) compute t = x @ W_in^T (+ bn1 stats, slot 0);
// blocks [512,1536) run the pos-MLP edge pass (g_pe + posBN stats, slot 1).
__global__ __launch_bounds__(256) void k_front(
        const float* __restrict__ x, const float* __restrict__ W_in,
        float* __restrict__ t_out,
        const float* __restrict__ pos, const int* __restrict__ src,
        const float* __restrict__ pw1, const float* __restrict__ pb1) {
    __shared__ __align__(16) float shT[128][68];
    __shared__ __align__(16) float shW[64][68];
    __shared__ float shS[2][64];
    int tid = threadIdx.x;

    if (blockIdx.x < 512) {
        int row0 = blockIdx.x * 128;
        if (tid < 64) { shS[0][tid] = 0.f; shS[1][tid] = 0.f; }

        for (int idx = tid; idx < 2048; idx += 256) {
            int r = idx >> 4, i4 = (idx & 15) * 4;
            float4 v = *(const float4*)&x[(row0 + r)*64 + i4];
            *(float4*)&shT[r][i4] = v;
        }
        for (int idx = tid; idx < 4096; idx += 256) {
            int o = idx >> 6, k = idx & 63;
            int q = o >> 2;
            int po = (((q >> 1) + ((q & 1) << 3)) << 2) + (o & 3);
            shW[k][po] = W_in[idx];
        }
        __syncthreads();

        int w = tid >> 5, lane = tid & 31;
        int g = lane >> 3, t = lane & 7;
        int rbase = w*16 + g;
        int c0 = t * 8;

        u64 acc2[4][4] = {};
        #pragma unroll 4
        for (int k = 0; k < 64; k++) {
            ulonglong2 B0 = *(const ulonglong2*)&shW[k][t*4];
            ulonglong2 B1 = *(const ulonglong2*)&shW[k][32 + t*4];
            #pragma unroll
            for (int i = 0; i < 4; i++) {
                float av = shT[rbase + 4*i][k];
                u64 av2 = pk2(av, av);
                acc2[i][0] = f2(av2, B0.x, acc2[i][0]);
                acc2[i][1] = f2(av2, B0.y, acc2[i][1]);
                acc2[i][2] = f2(av2, B1.x, acc2[i][2]);
                acc2[i][3] = f2(av2, B1.y, acc2[i][3]);
            }
        }
        float s[8] = {}, q2[8] = {};
        #pragma unroll
        for (int i = 0; i < 4; i++) {
            int rr = row0 + rbase + 4*i;
            float v[8];
            up2(acc2[i][0], v[0], v[1]);
            up2(acc2[i][1], v[2], v[3]);
            up2(acc2[i][2], v[4], v[5]);
            up2(acc2[i][3], v[6], v[7]);
            #pragma unroll
            for (int j = 0; j < 8; j++) { s[j] += v[j]; q2[j] += v[j]*v[j]; }
            *(float4*)&t_out[rr*64 + c0]     = make_float4(v[0],v[1],v[2],v[3]);
            *(float4*)&t_out[rr*64 + c0 + 4] = make_float4(v[4],v[5],v[6],v[7]);
        }
        #pragma unroll
        for (int j = 0; j < 8; j++) {
            s[j]  += __shfl_xor_sync(0xffffffffu, s[j], 8);
            s[j]  += __shfl_xor_sync(0xffffffffu, s[j], 16);
            q2[j] += __shfl_xor_sync(0xffffffffu, q2[j], 8);
            q2[j] += __shfl_xor_sync(0xffffffffu, q2[j], 16);
        }
        if (g == 0) {
            #pragma unroll
            for (int j = 0; j < 8; j++) {
                atomicAdd(&shS[0][c0+j], s[j]);
                atomicAdd(&shS[1][c0+j], q2[j]);
            }
        }
        __syncthreads();
        if (tid < 64) {
            atomicAdd(&g_sum[tid], (double)shS[0][tid]);
            atomicAdd(&g_ssq[tid], (double)shS[1][tid]);
        }
    } else {
        float w00=pw1[0],w01=pw1[1],w02=pw1[2];
        float w10=pw1[3],w11=pw1[4],w12=pw1[5];
        float w20=pw1[6],w21=pw1[7],w22=pw1[8];
        float b0=pb1[0],b1=pb1[1],b2=pb1[2];
        float s0=0,s1=0,s2=0,q0=0,q1=0,q2=0;
        int pbid = blockIdx.x - 512;
        int stride = 1024*256;
        for (int e = pbid*256 + tid; e < EE; e += stride) {
            int sj = src[e]; int di = e >> 4;
            float rx = pos[sj*3+0]-pos[di*3+0];
            float ry = pos[sj*3+1]-pos[di*3+1];
            float rz = pos[sj*3+2]-pos[di*3+2];
            float v0 = fmaf(rx,w00,fmaf(ry,w01,fmaf(rz,w02,b0)));
            float v1 = fmaf(rx,w10,fmaf(ry,w11,fmaf(rz,w12,b1)));
            float v2 = fmaf(rx,w20,fmaf(ry,w21,fmaf(rz,w22,b2)));
            g_pe[e] = v0; g_pe[EE+e] = v1; g_pe[2*EE+e] = v2;
            s0+=v0; q0+=v0*v0; s1+=v1; q1+=v1*v1; s2+=v2; q2+=v2*v2;
        }
        if (tid < 6) shS[0][tid]=0.f;
        __syncthreads();
        #pragma unroll
        for (int o = 16; o; o >>= 1) {
            s0+=__shfl_xor_sync(~0u,s0,o); s1+=__shfl_xor_sync(~0u,s1,o); s2+=__shfl_xor_sync(~0u,s2,o);
            q0+=__shfl_xor_sync(~0u,q0,o); q1+=__shfl_xor_sync(~0u,q1,o); q2+=__shfl_xor_sync(~0u,q2,o);
        }
        if ((tid & 31) == 0) {
            atomicAdd(&shS[0][0],s0); atomicAdd(&shS[0][1],s1); atomicAdd(&shS[0][2],s2);
            atomicAdd(&shS[0][3],q0); atomicAdd(&shS[0][4],q1); atomicAdd(&shS[0][5],q2);
        }
        __syncthreads();
        if (tid < 3) {
            atomicAdd(&g_sum[64+tid], (double)shS[0][tid]);
            atomicAdd(&g_ssq[64+tid], (double)shS[0][tid+3]);
        }
    }
}

// ---------------------------------------------------------------------------
__device__ __forceinline__ void compute_pos_bn(float* sP, const float* pbnG, const float* pbnB, int tid) {
    if (tid < 3) {
        double mu  = g_sum[64+tid] * (1.0/EE);
        double var = g_ssq[64+tid] * (1.0/EE) - mu*mu;
        float sc = pbnG[tid] * rsqrtf((float)var + BNEPS);
        sP[tid] = sc; sP[3+tid] = pbnB[tid] - (float)mu*sc;
    }
}

// ---------------------------------------------------------------------------
// stats of a = a_src[src] - a_dst[dst] + delta over E (slot 2). f32x2 math.
// Software-pipelined: next node's adst row + src vector prefetched during
// the current node's 16-edge processing (hides ~250cyc L2 latency).
__global__ __launch_bounds__(256) void k_attn1_stats(const int* __restrict__ src,
        const float* __restrict__ pw2, const float* __restrict__ pb2,
        const float* __restrict__ pbnG, const float* __restrict__ pbnB) {
    __shared__ float sh[2][64];
    __shared__ float sP[6];
    int tid = threadIdx.x, lane = tid & 31;
    compute_pos_bn(sP, pbnG, pbnB, tid);
    __syncthreads();
    int l = lane & 15, hl = lane >> 4;
    int c4 = l * 4;
    u64 PA[3], PB[3];
    #pragma unroll
    for (int k = 0; k < 3; k++) {
        PA[k] = pk2(pw2[(c4+0)*3+k], pw2[(c4+1)*3+k]);
        PB[k] = pk2(pw2[(c4+2)*3+k], pw2[(c4+3)*3+k]);
    }
    u64 Ab01 = pk2(pb2[c4+0], pb2[c4+1]);
    u64 Ab23 = pk2(pb2[c4+2], pb2[c4+3]);
    float ps0=sP[0],ps1=sP[1],ps2=sP[2];
    float pB0=sP[3],pB1=sP[4],pB2=sP[5];
    u64 s01=0, s23=0, q01=0, q23=0;
    int wId = (blockIdx.x*256 + tid) >> 5;
    int nW  = (gridDim.x*256) >> 5;
    // prologue loads for first node
    ulonglong2 adv = *(const ulonglong2*)&g_adst[wId*64 + c4];
    int sv = src[wId*16 + l];
    for (int n = wId; n < NN; n += nW) {
        int n2 = n + nW;
        ulonglong2 adv_nx; int sv_nx;
        if (n2 < NN) {
            adv_nx = *(const ulonglong2*)&g_adst[n2*64 + c4];
            sv_nx  = src[n2*16 + l];
        }
        u64 AbAd01 = ad2(Ab01, adv.x ^ SIGN2);
        u64 AbAd23 = ad2(Ab23, adv.y ^ SIGN2);
        #pragma unroll
        for (int jj = 0; jj < 8; jj++) {
            int ei = jj*2 + hl;
            int e  = n*16 + ei;
            int sj = __shfl_sync(0xffffffffu, sv, ei);
            float d0 = fmaxf(fmaf(g_pe[e],      ps0, pB0), 0.f);
            float d1 = fmaxf(fmaf(g_pe[EE+e],   ps1, pB1), 0.f);
            float d2 = fmaxf(fmaf(g_pe[2*EE+e], ps2, pB2), 0.f);
            u64 D0 = pk2(d0,d0), D1 = pk2(d1,d1), D2 = pk2(d2,d2);
            ulonglong2 asv = *(const ulonglong2*)&g_asrc[sj*64 + c4];
            u64 a01 = ad2(asv.x, f2(D0,PA[0], f2(D1,PA[1], f2(D2,PA[2], AbAd01))));
            u64 a23 = ad2(asv.y, f2(D0,PB[0], f2(D1,PB[1], f2(D2,PB[2], AbAd23))));
            s01 = ad2(s01, a01); q01 = f2(a01, a01, q01);
            s23 = ad2(s23, a23); q23 = f2(a23, a23, q23);
        }
        adv = adv_nx; sv = sv_nx;
    }
    float s[4], q[4];
    up2(s01, s[0], s[1]); up2(s23, s[2], s[3]);
    up2(q01, q[0], q[1]); up2(q23, q[2], q[3]);
    if (tid < 128) sh[tid>>6][tid&63] = 0.f;
    __syncthreads();
    #pragma unroll
    for (int i = 0; i < 4; i++) {
        s[i] += __shfl_xor_sync(0xffffffffu, s[i], 16);
        q[i] += __shfl_xor_sync(0xffffffffu, q[i], 16);
    }
    if (hl == 0) {
        #pragma unroll
        for (int i = 0; i < 4; i++) {
            atomicAdd(&sh[0][c4+i], s[i]);
            atomicAdd(&sh[1][c4+i], q[i]);
        }
    }
    __syncthreads();
    if (tid < 64) {
        atomicAdd(&g_sum[128+tid], (double)sh[0][tid]);
        atomicAdd(&g_ssq[128+tid], (double)sh[1][tid]);
    }
}

// ---------------------------------------------------------------------------
// a1 = relu(bn(a)) @ attn_w1^T + b1 -> g_a1 [E,8]; stats slot 3.
// Software-pipelined like k_attn1_stats.
__global__ __launch_bounds__(256) void k_a1(const int* __restrict__ src,
        const float* __restrict__ pw2, const float* __restrict__ pb2,
        const float* __restrict__ aw1, const float* __restrict__ ab1,
        const float* __restrict__ pbnG, const float* __restrict__ pbnB,
        const float* __restrict__ a1G, const float* __restrict__ a1B) {
    __shared__ float shQ[2][8];
    __shared__ float sP[6];
    __shared__ float sA[2][64];
    int tid = threadIdx.x, lane = tid & 31;
    compute_pos_bn(sP, pbnG, pbnB, tid);
    if (tid < 64) {
        double mu  = g_sum[128+tid] * (1.0/EE);
        double var = g_ssq[128+tid] * (1.0/EE) - mu*mu;
        float sc = a1G[tid] * rsqrtf((float)var + BNEPS);
        sA[0][tid] = sc; sA[1][tid] = a1B[tid] - (float)mu*sc;
    }
    __syncthreads();
    int l = lane & 15, hl = lane >> 4;
    int c4 = l * 4;
    u64 PA[3], PB[3];
    #pragma unroll
    for (int k = 0; k < 3; k++) {
        PA[k] = pk2(pw2[(c4+0)*3+k], pw2[(c4+1)*3+k]);
        PB[k] = pk2(pw2[(c4+2)*3+k], pw2[(c4+3)*3+k]);
    }
    u64 Ab01 = pk2(pb2[c4+0], pb2[c4+1]);
    u64 Ab23 = pk2(pb2[c4+2], pb2[c4+3]);
    float ps0=sP[0],ps1=sP[1],ps2=sP[2];
    float pB0=sP[3],pB1=sP[4],pB2=sP[5];
    float sc[4], sb[4];
    #pragma unroll
    for (int i = 0; i < 4; i++) { sc[i]=sA[0][c4+i]; sb[i]=sA[1][c4+i]; }
    u64 WT[4][4];
    #pragma unroll
    for (int jp = 0; jp < 4; jp++)
        #pragma unroll
        for (int c = 0; c < 4; c++)
            WT[c][jp] = pk2(aw1[(2*jp)*64 + c4 + c], aw1[(2*jp+1)*64 + c4 + c]);
    int jown = l >> 1;
    float bj = ab1[jown];
    float st = 0.f, sq = 0.f;
    int wId = (blockIdx.x*256 + tid) >> 5;
    int nW  = (gridDim.x*256) >> 5;
    ulonglong2 adv = *(const ulonglong2*)&g_adst[wId*64 + c4];
    int sv = src[wId*16 + l];
    for (int n = wId; n < NN; n += nW) {
        int n2 = n + nW;
        ulonglong2 adv_nx; int sv_nx;
        if (n2 < NN) {
            adv_nx = *(const ulonglong2*)&g_adst[n2*64 + c4];
            sv_nx  = src[n2*16 + l];
        }
        u64 AbAd01 = ad2(Ab01, adv.x ^ SIGN2);
        u64 AbAd23 = ad2(Ab23, adv.y ^ SIGN2);
        #pragma unroll
        for (int jj = 0; jj < 8; jj++) {
            int ei = jj*2 + hl;
            int e  = n*16 + ei;
            int sj = __shfl_sync(0xffffffffu, sv, ei);
            float d0 = fmaxf(fmaf(g_pe[e],      ps0, pB0), 0.f);
            float d1 = fmaxf(fmaf(g_pe[EE+e],   ps1, pB1), 0.f);
            float d2 = fmaxf(fmaf(g_pe[2*EE+e], ps2, pB2), 0.f);
            u64 D0 = pk2(d0,d0), D1 = pk2(d1,d1), D2 = pk2(d2,d2);
            ulonglong2 asv = *(const ulonglong2*)&g_asrc[sj*64 + c4];
            u64 a01 = ad2(asv.x, f2(D0,PA[0], f2(D1,PA[1], f2(D2,PA[2], AbAd01))));
            u64 a23 = ad2(asv.y, f2(D0,PB[0], f2(D1,PB[1], f2(D2,PB[2], AbAd23))));
            float aa0, aa1, aa2, aa3;
            up2(a01, aa0, aa1); up2(a23, aa2, aa3);
            float r0 = fmaxf(fmaf(aa0, sc[0], sb[0]), 0.f);
            float r1 = fmaxf(fmaf(aa1, sc[1], sb[1]), 0.f);
            float r2 = fmaxf(fmaf(aa2, sc[2], sb[2]), 0.f);
            float r3 = fmaxf(fmaf(aa3, sc[3], sb[3]), 0.f);
            u64 R0 = pk2(r0,r0), R1 = pk2(r1,r1), R2 = pk2(r2,r2), R3 = pk2(r3,r3);
            float p[8];
            #pragma unroll
            for (int jp = 0; jp < 4; jp++) {
                u64 t2 = f2(R0, WT[0][jp], f2(R1, WT[1][jp], f2(R2, WT[2][jp], f2(R3, WT[3][jp], 0ull))));
                up2(t2, p[2*jp], p[2*jp+1]);
            }
            #pragma unroll
            for (int j = 0; j < 4; j++) {
                float v = (l & 8) ? p[j] : p[j+4];
                float ww = __shfl_xor_sync(0xffffffffu, v, 8);
                p[j] = ((l & 8) ? p[j+4] : p[j]) + ww;
            }
            #pragma unroll
            for (int j = 0; j < 2; j++) {
                float v = (l & 4) ? p[j] : p[j+2];
                float ww = __shfl_xor_sync(0xffffffffu, v, 4);
                p[j] = ((l & 4) ? p[j+2] : p[j]) + ww;
            }
            {
                float v = (l & 2) ? p[0] : p[1];
                float ww = __shfl_xor_sync(0xffffffffu, v, 2);
                p[0] = ((l & 2) ? p[1] : p[0]) + ww;
            }
            p[0] += __shfl_xor_sync(0xffffffffu, p[0], 1);
            float vv = p[0] + bj;
            if ((l & 1) == 0) {
                g_a1[e*8 + jown] = vv;
                st += vv; sq += vv*vv;
            }
        }
        adv = adv_nx; sv = sv_nx;
    }
    if (tid < 16) shQ[tid>>3][tid&7] = 0.f;
    __syncthreads();
    if ((l & 1) == 0) { atomicAdd(&shQ[0][jown], st); atomicAdd(&shQ[1][jown], sq); }
    __syncthreads();
    if (tid < 8) {
        atomicAdd(&g_sum[192+tid], (double)shQ[0][tid]);
        atomicAdd(&g_ssq[192+tid], (double)shQ[1][tid]);
    }
}

// ---------------------------------------------------------------------------
// Warp-per-node: a2 from a1, softmax (16 edges), weighted aggregation; stats slot 4.
__global__ __launch_bounds__(256) void k_aggr(const int* __restrict__ src,
        const float* __restrict__ pw2, const float* __restrict__ pb2,
        const float* __restrict__ aw2, const float* __restrict__ ab2,
        const float* __restrict__ pbnG, const float* __restrict__ pbnB,
        const float* __restrict__ a2G, const float* __restrict__ a2B) {
    __shared__ float sh_alpha[8][16][8];
    __shared__ float sh_d[8][16][3];
    __shared__ float shS[2][64];
    __shared__ float sP[6];
    __shared__ float sB[2][8];
    int tid = threadIdx.x, lane = tid & 31, w = tid >> 5;
    compute_pos_bn(sP, pbnG, pbnB, tid);
    if (tid < 8) {
        double mu  = g_sum[192+tid] * (1.0/EE);
        double var = g_ssq[192+tid] * (1.0/EE) - mu*mu;
        float sc = a2G[tid] * rsqrtf((float)var + BNEPS);
        sB[0][tid] = sc; sB[1][tid] = a2B[tid] - (float)mu*sc;
    }
    if (tid < 128) shS[tid>>6][tid&63] = 0.f;
    __syncthreads();
    int c = lane, c2 = lane + 32;
    float A0=pw2[c*3],  A1=pw2[c*3+1],  A2=pw2[c*3+2],  Abc=pb2[c];
    float B0=pw2[c2*3], B1=pw2[c2*3+1], B2=pw2[c2*3+2], Bbc=pb2[c2];
    float ps0=sP[0],ps1=sP[1],ps2=sP[2];
    float pB0=sP[3],pB1=sP[4],pB2=sP[5];
    int e = lane >> 1, j4 = (lane & 1) * 4;
    float s3[4], b3[4];
    #pragma unroll
    for (int i = 0; i < 4; i++) { s3[i]=sB[0][j4+i]; b3[i]=sB[1][j4+i]; }
    float4 w2v[8];
    #pragma unroll
    for (int j = 0; j < 8; j++) w2v[j] = *(const float4*)&aw2[j*8 + j4];
    float b2v[8];
    #pragma unroll
    for (int j = 0; j < 8; j++) b2v[j] = ab2[j];
    int j8 = lane & 7;
    float st=0, sq=0, st2=0, sq2=0;
    int wId = blockIdx.x*8 + w, nW = gridDim.x*8;
    for (int n = wId; n < NN; n += nW) {
        int sv = src[n*16 + (lane & 15)];
        if (lane < 16) {
            int ee = n*16 + lane;
            sh_d[w][lane][0] = fmaxf(fmaf(g_pe[ee],      ps0, pB0), 0.f);
            sh_d[w][lane][1] = fmaxf(fmaf(g_pe[EE+ee],   ps1, pB1), 0.f);
            sh_d[w][lane][2] = fmaxf(fmaf(g_pe[2*EE+ee], ps2, pB2), 0.f);
        }
        float4 bv = *(const float4*)&g_a1[n*128 + lane*4];
        float bb0 = fmaxf(fmaf(bv.x, s3[0], b3[0]), 0.f);
        float bb1 = fmaxf(fmaf(bv.y, s3[1], b3[1]), 0.f);
        float bb2 = fmaxf(fmaf(bv.z, s3[2], b3[2]), 0.f);
        float bb3 = fmaxf(fmaf(bv.w, s3[3], b3[3]), 0.f);
        float p[8];
        #pragma unroll
        for (int j = 0; j < 8; j++)
            p[j] = fmaf(bb0, w2v[j].x, fmaf(bb1, w2v[j].y, fmaf(bb2, w2v[j].z, bb3 * w2v[j].w)));
        #pragma unroll
        for (int j = 0; j < 8; j++) p[j] += __shfl_xor_sync(0xffffffffu, p[j], 1);
        if ((lane & 1) == 0) {
            #pragma unroll
            for (int j = 0; j < 8; j++) sh_alpha[w][e][j] = p[j] + b2v[j];
        }
        __syncwarp();
        if (lane < 8) {
            float mx = -1e30f;
            #pragma unroll
            for (int t = 0; t < 16; t++) mx = fmaxf(mx, sh_alpha[w][t][lane]);
            float ex[16], sm = 0.f;
            #pragma unroll
            for (int t = 0; t < 16; t++) { ex[t] = __expf(sh_alpha[w][t][lane]-mx); sm += ex[t]; }
            float inv = 1.f/sm;
            #pragma unroll
            for (int t = 0; t < 16; t++) sh_alpha[w][t][lane] = ex[t]*inv;
        }
        __syncwarp();
        float acc = 0.f, acc2 = 0.f;
        #pragma unroll
        for (int t = 0; t < 16; t++) {
            int sj = __shfl_sync(0xffffffffu, sv, t);
            float hw  = g_hW[sj*64 + c];
            float hw2 = g_hW[sj*64 + c2];
            float d0 = sh_d[w][t][0], d1 = sh_d[w][t][1], d2 = sh_d[w][t][2];
            float al = sh_alpha[w][t][j8];
            acc  = fmaf(al, hw  + fmaf(d0,A0,fmaf(d1,A1,fmaf(d2,A2,Abc))), acc);
            acc2 = fmaf(al, hw2 + fmaf(d0,B0,fmaf(d1,B1,fmaf(d2,B2,Bbc))), acc2);
        }
        g_aggr[n*64 + c]  = acc;
        g_aggr[n*64 + c2] = acc2;
        st += acc; sq += acc*acc; st2 += acc2; sq2 += acc2*acc2;
        __syncwarp();
    }
    __syncthreads();
    atomicAdd(&shS[0][c],  st);  atomicAdd(&shS[1][c],  sq);
    atomicAdd(&shS[0][c2], st2); atomicAdd(&shS[1][c2], sq2);
    __syncthreads();
    if (tid < 64) {
        atomicAdd(&g_sum[256+tid], (double)shS[0][tid]);
        atomicAdd(&g_ssq[256+tid], (double)shS[1][tid]);
    }
}

// ---------------------------------------------------------------------------
__global__ __launch_bounds__(256) void k_final(const float* __restrict__ x,
        const float* __restrict__ g, const float* __restrict__ b,
        float* __restrict__ out) {
    __shared__ float sSc[64], sBi[64];
    int tid = threadIdx.x;
    if (tid < 64) {
        double mu  = g_sum[5*64+tid] * (1.0/NN);
        double var = g_ssq[5*64+tid] * (1.0/NN) - mu*mu;
        float sc = g[tid] * rsqrtf((float)var + BNEPS);
        sSc[tid] = sc; sBi[tid] = b[tid] - (float)mu*sc;
    }
    __syncthreads();
    int stride = gridDim.x * blockDim.x;
    for (int i4 = blockIdx.x*blockDim.x + tid; i4 < NN*16; i4 += stride) {
        float4 v  = *(const float4*)&g_t3[i4*4];
        float4 xv = *(const float4*)&x[i4*4];
        int cg = (i4 & 15) * 4;
        float4 r;
        r.x = fmaxf(fmaf(v.x, sSc[cg+0], sBi[cg+0]) + xv.x, 0.f);
        r.y = fmaxf(fmaf(v.y, sSc[cg+1], sBi[cg+1]) + xv.y, 0.f);
        r.z = fmaxf(fmaf(v.z, sSc[cg+2], sBi[cg+2]) + xv.z, 0.f);
        r.w = fmaxf(fmaf(v.w, sSc[cg+3], sBi[cg+3]) + xv.w, 0.f);
        *(float4*)&out[i4*4] = r;
    }
}

// ---------------------------------------------------------------------------
extern "C" void kernel_launch(void* const* d_in, const int* in_sizes, int n_in,
                              void* d_out, int out_size) {
    const float* x      = (const float*)d_in[0];
    const float* pos    = (const float*)d_in[1];
    const int*   src    = (const int*)  d_in[2];
    const float* W_in   = (const float*)d_in[3];
    const float* W_out  = (const float*)d_in[4];
    const float* pw1    = (const float*)d_in[5];
    const float* pb1    = (const float*)d_in[6];
    const float* pbn_g  = (const float*)d_in[7];
    const float* pbn_b  = (const float*)d_in[8];
    const float* pw2    = (const float*)d_in[9];
    const float* pb2    = (const float*)d_in[10];
    const float* abn1_g = (const float*)d_in[11];
    const float* abn1_b = (const float*)d_in[12];
    const float* aw1    = (const float*)d_in[13];
    const float* ab1    = (const float*)d_in[14];
    const float* abn2_g = (const float*)d_in[15];
    const float* abn2_b = (const float*)d_in[16];
    const float* aw2    = (const float*)d_in[17];
    const float* ab2    = (const float*)d_in[18];
    const float* lin_w  = (const float*)d_in[19];
    const float* lin_b  = (const float*)d_in[20];
    const float* src_w  = (const float*)d_in[21];
    const float* src_b  = (const float*)d_in[22];
    const float* dst_w  = (const float*)d_in[23];
    const float* dst_b  = (const float*)d_in[24];
    const float* bn1_g  = (const float*)d_in[25];
    const float* bn1_b  = (const float*)d_in[26];
    const float* bn2_g  = (const float*)d_in[27];
    const float* bn2_b  = (const float*)d_in[28];
    const float* bn3_g  = (const float*)d_in[29];
    const float* bn3_b  = (const float*)d_in[30];
    float* out = (float*)d_out;

    float *p_t, *p_asrc, *p_adst, *p_hW, *p_aggr, *p_t3;
    cudaGetSymbolAddress((void**)&p_t,    g_t);
    cudaGetSymbolAddress((void**)&p_asrc, g_asrc);
    cudaGetSymbolAddress((void**)&p_adst, g_adst);
    cudaGetSymbolAddress((void**)&p_hW,   g_hW);
    cudaGetSymbolAddress((void**)&p_aggr, g_aggr);
    cudaGetSymbolAddress((void**)&p_t3,   g_t3);

    k_zero<<<1,384>>>();

    // fused: t = x @ W_in^T (+ bn1 stats)  ||  pos MLP + posBN stats
    k_front<<<1536,256>>>(x, W_in, p_t, pos, src, pw1, pb1);

    // a_src/a_dst/hW = relu(bn1(t)) @ {src_w,dst_w,lin_w}^T + bias (fused triple)
    k_gemm<<<512,256>>>(p_t, src_w, src_b, p_asrc,
                        dst_w, dst_b, p_adst,
                        lin_w, lin_b, p_hW,
                        0, bn1_g, bn1_b, -1);

    // attn_bn1 stats over edges
    k_attn1_stats<<<1024,256>>>(src, pw2, pb2, pbn_g, pbn_b);

    // a1 ; attn_bn2 stats
    k_a1<<<1024,256>>>(src, pw2, pb2, aw1, ab1, pbn_g, pbn_b, abn1_g, abn1_b);

    // softmax + aggregation ; bn2 stats
    k_aggr<<<1024,256>>>(src, pw2, pb2, aw2, ab2, pbn_g, pbn_b, abn2_g, abn2_b);

    // t3 = relu(bn2(aggr)) @ W_out^T ; bn3 stats
    k_gemm<<<512,256>>>(p_aggr, W_out, nullptr, p_t3,
                        nullptr, nullptr, nullptr, nullptr, nullptr, nullptr,
                        4, bn2_g, bn2_b, 5);

    // y = relu(bn3(t3) + x)
    k_final<<<1024,256>>>(x, bn3_g, bn3_b, out);
}